// round 10
// baseline (speedup 1.0000x reference)
#include <cuda_runtime.h>
#include <cuda_bf16.h>
#include <math.h>

#define MAXN 50000
#define MAXE 800000
#define SCAN_TILE 4096

// ---------------- scratch (device globals; no allocation allowed) ----------------
__device__ int   g_is64;
__device__ __align__(16) int2  g_sd[MAXE];   // (src, dst) original order
__device__ int   g_rowptr[MAXN + 1];
__device__ int   g_cursor[MAXN];
__device__ int2  g_pair[MAXE];               // (src, ea-bits) sorted by dst
__device__ __align__(16) float g_xl2[(size_t)MAXN * 128];
__device__ __align__(16) float g_xr2[(size_t)MAXN * 128];
__device__ float g_p[MAXN];
__device__ float g_q[MAXN];
__device__ __align__(16) float4 g_cpack[64];
__device__ float g_aggA[64];
__device__ float g_aggC[64];
__device__ float g_u2[128];
__device__ float g_v2[128];

// ---------------- precompute + int64 detect + cursor zero (fused) ----------------
__global__ void k_prez(const float* __restrict__ W_em, const float* __restrict__ b_em,
                       const float* __restrict__ W0,   const float* __restrict__ b0,
                       const float* __restrict__ Wl1,  const float* __restrict__ bl1,
                       const float* __restrict__ Wr1,  const float* __restrict__ br1,
                       const float* __restrict__ We1,  const float* __restrict__ We2,
                       const void* __restrict__ ei, int N)
{
    int i = blockIdx.x * blockDim.x + threadIdx.x;
    if (i < N) g_cursor[i] = 0;
    if (blockIdx.x != 0) return;
    int t = threadIdx.x;
    if (t == 0) {
        const long long* p = (const long long*)ei;
        int is64 = 1;
        for (int k = 0; k < 8; k++) {
            long long v = p[k];
            if (v < 0 || v >= (1LL << 31)) { is64 = 0; break; }
        }
        g_is64 = is64;
    }
    if (t < 64) {
        float cS = 0.f, cD = 0.f, cE = 0.f;
        float Cl = bl1[t], Cr = br1[t], v1 = 0.f;
        for (int k = 0; k < 128; k++) {
            float wl = Wl1[k * 64 + t];
            float wr = Wr1[k * 64 + t];
            float we = We1[k * 64 + t];
            cS += W0[k]   * wl;
            cD += W0[k]   * wr;
            cE += W_em[k] * we;
            Cl += b0[k]   * wl;
            Cr += b0[k]   * wr;
            v1 += b_em[k] * we;
        }
        g_cpack[t] = make_float4(cS, cD, cE, Cl + Cr + v1);
        g_aggA[t] = cS;
        g_aggC[t] = Cl;
    }
    if (t >= 128 && t < 256) {
        int c = t - 128;
        float u = 0.f, v = 0.f;
        for (int k = 0; k < 128; k++) {
            float w = We2[k * 128 + c];
            u += W_em[k] * w;
            v += b_em[k] * w;
        }
        g_u2[c] = u;
        g_v2[c] = v;
    }
}

// ---------------- CSR build: 2 edges per thread ----------------
__global__ void k_convert(const void* __restrict__ ei, int E) {
    int t = blockIdx.x * blockDim.x + threadIdx.x;
    int e = 2 * t;
    if (e >= E) return;
    bool two = (e + 1 < E);
    int evenE = !(E & 1);
    int s0, d0, s1 = 0, d1 = 0;
    if (g_is64) {
        const long long* p = (const long long*)ei;
        longlong2 sv = ((const longlong2*)p)[t];
        s0 = (int)sv.x;
        if (two) s1 = (int)sv.y;
        if (evenE) {
            longlong2 dv = ((const longlong2*)(p + E))[t];
            d0 = (int)dv.x;
            if (two) d1 = (int)dv.y;
        } else {
            d0 = (int)p[E + e];
            if (two) d1 = (int)p[E + e + 1];
        }
    } else {
        const int* p = (const int*)ei;
        int2 sv = ((const int2*)p)[t];
        s0 = sv.x;
        if (two) s1 = sv.y;
        if (evenE) {
            int2 dv = ((const int2*)(p + E))[t];
            d0 = dv.x;
            if (two) d1 = dv.y;
        } else {
            d0 = p[E + e];
            if (two) d1 = p[E + e + 1];
        }
    }
    if (two) {
        ((int4*)g_sd)[t] = make_int4(s0, d0, s1, d1);
        atomicAdd(&g_cursor[d0], 1);
        atomicAdd(&g_cursor[d1], 1);
    } else {
        g_sd[e] = make_int2(s0, d0);
        atomicAdd(&g_cursor[d0], 1);
    }
}

// ---------------- single-block multi-tile scan (coalesced, shared carry) ----------------
__global__ void k_scan1b(int n) {
    __shared__ int s[SCAN_TILE];
    __shared__ int ws[32];
    __shared__ int s_carry;
    int tid = threadIdx.x;                  // 1024
    int lane = tid & 31, w = tid >> 5;
    if (tid == 0) s_carry = 0;
    __syncthreads();
    int nb = (n + SCAN_TILE - 1) / SCAN_TILE;
    for (int b = 0; b < nb; b++) {
        int base = b * SCAN_TILE;
        #pragma unroll
        for (int k = 0; k < 4; k++) {
            int i = base + tid + k * 1024;
            s[tid + k * 1024] = (i < n) ? g_cursor[i] : 0;
        }
        __syncthreads();
        int a0 = s[4 * tid], a1 = s[4 * tid + 1], a2 = s[4 * tid + 2], a3 = s[4 * tid + 3];
        int tsum = a0 + a1 + a2 + a3;
        int incl = tsum;
        #pragma unroll
        for (int off = 1; off < 32; off <<= 1) {
            int t = __shfl_up_sync(0xffffffffu, incl, off);
            if (lane >= off) incl += t;
        }
        if (lane == 31) ws[w] = incl;
        __syncthreads();
        if (w == 0) {
            int y = ws[lane];
            #pragma unroll
            for (int off = 1; off < 32; off <<= 1) {
                int t = __shfl_up_sync(0xffffffffu, y, off);
                if (lane >= off) y += t;
            }
            ws[lane] = y;
        }
        __syncthreads();
        int run = s_carry + incl - tsum + (w > 0 ? ws[w - 1] : 0);
        int pref[4] = {run, run + a0, run + a0 + a1, run + a0 + a1 + a2};
        #pragma unroll
        for (int k = 0; k < 4; k++) {
            int i = base + 4 * tid + k;
            if (i < n) { g_rowptr[i] = pref[k]; g_cursor[i] = pref[k]; }
        }
        __syncthreads();
        if (tid == 0) s_carry += ws[31];
        __syncthreads();
    }
    if (tid == 0) g_rowptr[n] = s_carry;
}

// ---------------- scatter: 2 edges per thread ----------------
__global__ void k_scatter(const float* __restrict__ ea, int E) {
    int t = blockIdx.x * blockDim.x + threadIdx.x;
    int e = 2 * t;
    if (e >= E) return;
    if (e + 1 < E) {
        int4 sd2 = ((const int4*)g_sd)[t];
        float2 av = ((const float2*)ea)[t];
        int pos0 = atomicAdd(&g_cursor[sd2.y], 1);
        int pos1 = atomicAdd(&g_cursor[sd2.w], 1);
        g_pair[pos0] = make_int2(sd2.x, __float_as_int(av.x));
        g_pair[pos1] = make_int2(sd2.z, __float_as_int(av.y));
    } else {
        int2 sd = g_sd[e];
        int pos = atomicAdd(&g_cursor[sd.y], 1);
        g_pair[pos] = make_int2(sd.x, __float_as_int(ea[e]));
    }
}

// ---------------- fused layer1 + lin2: 64-node tile per block ----------------
// Phase 1 uses HALF-WARP (16-lane) groups per node: deg~16 keeps lanes busy.
__global__ void k_layer12(const float* __restrict__ x,
                          const float* __restrict__ att1, const float* __restrict__ bias1,
                          const float* __restrict__ Wl, const float* __restrict__ bl,
                          const float* __restrict__ Wr, const float* __restrict__ br,
                          int N)
{
    __shared__ float4 sc[64];
    __shared__ float  sa[64];
    __shared__ float  sb1[64];
    __shared__ float  sH[64 * 64];       // h1 tile, 16 KB
    int tid = threadIdx.x;               // 256
    if (tid < 64) { sc[tid] = g_cpack[tid]; sa[tid] = att1[tid]; sb1[tid] = bias1[tid]; }
    __syncthreads();
    int warp = tid >> 5, lane = tid & 31;
    int grp = lane >> 4, sl = lane & 15;   // half-warp group + sublane
    int tile0 = blockIdx.x * 64;

    // ---- phase 1: 2 nodes per warp per round, 4 rounds ----
    for (int r = 0; r < 4; r++) {
        int nl = warp * 8 + r * 2 + grp;       // local node 0..63
        int n = tile0 + nl;
        bool active = (n < N);
        int beg = 0, end = 0;
        float xd = 0.f;
        if (active) { beg = g_rowptr[n]; end = g_rowptr[n + 1]; xd = x[n]; }

        float mx[8], den[8], s1[8];
        #pragma unroll
        for (int h = 0; h < 8; h++) { mx[h] = -1e30f; den[h] = 0.f; s1[h] = 0.f; }

        int eix = beg + sl;
        for (; eix + 16 < end; eix += 32) {
            int2 p0 = g_pair[eix], p1 = g_pair[eix + 16];
            float xs0 = x[p0.x], xs1 = x[p1.x];
            float a0 = __int_as_float(p0.y), a1 = __int_as_float(p1.y);
            #pragma unroll
            for (int h = 0; h < 8; h++) {
                float v0 = 0.f, v1 = 0.f;
                #pragma unroll
                for (int c = 0; c < 8; c++) {
                    int j = h * 8 + c;
                    float4 q = sc[j];
                    float m0 = fmaf(q.x, xs0, fmaf(q.y, xd, fmaf(q.z, a0, q.w)));
                    float m1 = fmaf(q.x, xs1, fmaf(q.y, xd, fmaf(q.z, a1, q.w)));
                    m0 = m0 > 0.f ? m0 : 0.2f * m0;
                    m1 = m1 > 0.f ? m1 : 0.2f * m1;
                    v0 = fmaf(m0, sa[j], v0);
                    v1 = fmaf(m1, sa[j], v1);
                }
                float mb = fmaxf(v0, v1);
                float e0 = __expf(v0 - mb), e1 = __expf(v1 - mb);
                float mnew = fmaxf(mx[h], mb);
                float corr  = __expf(mx[h] - mnew);
                float scale = __expf(mb - mnew);
                den[h] = fmaf(den[h], corr, (e0 + e1) * scale);
                s1[h]  = fmaf(s1[h],  corr, fmaf(e0, xs0, e1 * xs1) * scale);
                mx[h] = mnew;
            }
        }
        if (eix < end) {
            int2 pr = g_pair[eix];
            float xs = x[pr.x];
            float a  = __int_as_float(pr.y);
            #pragma unroll
            for (int h = 0; h < 8; h++) {
                float scv = 0.f;
                #pragma unroll
                for (int c = 0; c < 8; c++) {
                    int j = h * 8 + c;
                    float4 q = sc[j];
                    float m = fmaf(q.x, xs, fmaf(q.y, xd, fmaf(q.z, a, q.w)));
                    m = m > 0.f ? m : 0.2f * m;
                    scv = fmaf(m, sa[j], scv);
                }
                float mnew = fmaxf(mx[h], scv);
                float corr = __expf(mx[h] - mnew);
                float ex   = __expf(scv - mnew);
                den[h] = fmaf(den[h], corr, ex);
                s1[h]  = fmaf(s1[h],  corr, ex * xs);
                mx[h] = mnew;
            }
        }
        // combine the 16 sublanes of this group (width-16 xor shuffles)
        #pragma unroll
        for (int h = 0; h < 8; h++) {
            float M = mx[h];
            #pragma unroll
            for (int off = 8; off; off >>= 1)
                M = fmaxf(M, __shfl_xor_sync(0xffffffffu, M, off, 16));
            float corr = __expf(mx[h] - M);
            float d2 = den[h] * corr;
            float s2 = s1[h]  * corr;
            #pragma unroll
            for (int off = 8; off; off >>= 1) {
                d2 += __shfl_xor_sync(0xffffffffu, d2, off, 16);
                s2 += __shfl_xor_sync(0xffffffffu, s2, off, 16);
            }
            den[h] = d2; s1[h] = s2;
        }

        if (active) {
            float s0 = (end > beg) ? 1.f : 0.f;
            #pragma unroll
            for (int rr = 0; rr < 4; rr++) {
                int j = sl + rr * 16;
                int h = j >> 3;
                float S1 = s1[h] / fmaxf(den[h], 1e-16f);
                float o = fmaf(g_aggA[j], S1, fmaf(g_aggC[j], s0, sb1[j]));
                o = o > 0.f ? o : expm1f(o);    // elu
                sH[nl * 64 + j] = o;
            }
        }
    }
    __syncthreads();

    // ---- phase 2: two GEMVs from smem h1 ----
    int half = tid >> 7;                   // 0 -> xl2, 1 -> xr2
    int col  = tid & 127;
    const float* W = half ? Wr : Wl;
    const float* b = half ? br : bl;
    float* out = half ? g_xr2 : g_xl2;

    float wcol[64];
    float bb = b[col];
    #pragma unroll
    for (int k = 0; k < 64; k++) wcol[k] = W[k * 128 + col];

    int rows = min(64, N - tile0);
    for (int r = 0; r < rows; r++) {
        const float4* rv4 = (const float4*)&sH[r * 64];
        float acc = bb;
        #pragma unroll
        for (int k4 = 0; k4 < 16; k4++) {
            float4 rv = rv4[k4];
            acc = fmaf(rv.x, wcol[4 * k4 + 0], acc);
            acc = fmaf(rv.y, wcol[4 * k4 + 1], acc);
            acc = fmaf(rv.z, wcol[4 * k4 + 2], acc);
            acc = fmaf(rv.w, wcol[4 * k4 + 3], acc);
        }
        out[(size_t)(tile0 + r) * 128 + col] = acc;
    }
}

// ---------------- layer 2 attention: float4 channels, batch-4 online softmax ----------------
__global__ void k_attn2(const float* __restrict__ att2,
                        const float* __restrict__ bias2, const float* __restrict__ Wd,
                        int N)
{
    __shared__ float su[128], sv[128], sat[128], sb2[128], swd[256];
    int tid = threadIdx.x;  // 256
    if (tid < 128) { su[tid] = g_u2[tid]; sv[tid] = g_v2[tid]; sat[tid] = att2[tid]; sb2[tid] = bias2[tid]; }
    if (tid < 256) swd[tid] = Wd[tid];
    __syncthreads();
    int warp = tid >> 5, lane = tid & 31;
    int n = blockIdx.x * 8 + warp;
    if (n >= N) return;
    int beg = g_rowptr[n], end = g_rowptr[n + 1];

    float4 xr = ((const float4*)(&g_xr2[(size_t)n * 128]))[lane];
    float u[4], v[4], at[4];
    #pragma unroll
    for (int k = 0; k < 4; k++) {
        int ch = 4 * lane + k;
        u[k] = su[ch]; v[k] = sv[ch]; at[k] = sat[ch];
    }
    float xrv[4] = {xr.x, xr.y, xr.z, xr.w};

    float mx = -1e30f, den = 0.f;
    float acc[4] = {0.f, 0.f, 0.f, 0.f};

    int ei = beg;
    for (; ei + 4 <= end; ei += 4) {
        float sc[4];
        float4 xlv[4];
        #pragma unroll
        for (int j = 0; j < 4; j++) {
            int2 pr = g_pair[ei + j];
            xlv[j] = ((const float4*)(&g_xl2[(size_t)pr.x * 128]))[lane];
            float a = __int_as_float(pr.y);
            const float* xv = (const float*)&xlv[j];
            float t = 0.f;
            #pragma unroll
            for (int k = 0; k < 4; k++) {
                float m = xv[k] + xrv[k] + fmaf(a, u[k], v[k]);
                m = m > 0.f ? m : 0.2f * m;
                t = fmaf(m, at[k], t);
            }
            sc[j] = t;
        }
        #pragma unroll
        for (int off = 16; off; off >>= 1) {
            #pragma unroll
            for (int j = 0; j < 4; j++)
                sc[j] += __shfl_xor_sync(0xffffffffu, sc[j], off);
        }
        float mb = fmaxf(fmaxf(sc[0], sc[1]), fmaxf(sc[2], sc[3]));
        float ex0 = __expf(sc[0] - mb), ex1 = __expf(sc[1] - mb);
        float ex2 = __expf(sc[2] - mb), ex3 = __expf(sc[3] - mb);
        float mnew = fmaxf(mx, mb);
        float corr  = __expf(mx - mnew);
        float scale = __expf(mb - mnew);
        den = fmaf(den, corr, (ex0 + ex1 + ex2 + ex3) * scale);
        #pragma unroll
        for (int k = 0; k < 4; k++) {
            float s = fmaf(ex0, ((const float*)&xlv[0])[k],
                      fmaf(ex1, ((const float*)&xlv[1])[k],
                      fmaf(ex2, ((const float*)&xlv[2])[k],
                           ex3 * ((const float*)&xlv[3])[k])));
            acc[k] = fmaf(acc[k], corr, s * scale);
        }
        mx = mnew;
    }
    for (; ei < end; ei++) {
        int2 pr = g_pair[ei];
        float4 xl4 = ((const float4*)(&g_xl2[(size_t)pr.x * 128]))[lane];
        const float* xv = (const float*)&xl4;
        float a = __int_as_float(pr.y);
        float sc = 0.f;
        #pragma unroll
        for (int k = 0; k < 4; k++) {
            float m = xv[k] + xrv[k] + fmaf(a, u[k], v[k]);
            m = m > 0.f ? m : 0.2f * m;
            sc = fmaf(m, at[k], sc);
        }
        #pragma unroll
        for (int off = 16; off; off >>= 1) sc += __shfl_xor_sync(0xffffffffu, sc, off);
        float mnew = fmaxf(mx, sc);
        float corr = __expf(mx - mnew);
        float ex   = __expf(sc - mnew);
        den = fmaf(den, corr, ex);
        #pragma unroll
        for (int k = 0; k < 4; k++) acc[k] = fmaf(acc[k], corr, ex * xv[k]);
        mx = mnew;
    }
    den = fmaxf(den, 1e-16f);

    float p = 0.f, q = 0.f;
    #pragma unroll
    for (int k = 0; k < 4; k++) {
        int ch = 4 * lane + k;
        float h2 = acc[k] / den + sb2[ch];
        p = fmaf(h2, swd[ch], p);
        q = fmaf(h2, swd[128 + ch], q);
    }
    #pragma unroll
    for (int off = 16; off; off >>= 1) {
        p += __shfl_xor_sync(0xffffffffu, p, off);
        q += __shfl_xor_sync(0xffffffffu, q, off);
    }
    if (lane == 0) { g_p[n] = p; g_q[n] = q; }
}

// ---------------- final edge output: 2 edges per thread ----------------
__global__ void k_final(const float* __restrict__ bd, float* __restrict__ out, int E) {
    int t = blockIdx.x * blockDim.x + threadIdx.x;
    int e = 2 * t;
    if (e >= E) return;
    float b = bd[0];
    if (e + 1 < E) {
        int4 sd2 = ((const int4*)g_sd)[t];
        float2 o;
        o.x = g_p[sd2.x] + g_q[sd2.y] + b;
        o.y = g_p[sd2.z] + g_q[sd2.w] + b;
        ((float2*)out)[t] = o;
    } else {
        int2 sd = g_sd[e];
        out[e] = g_p[sd.x] + g_q[sd.y] + b;
    }
}

// ---------------- launch ----------------
extern "C" void kernel_launch(void* const* d_in, const int* in_sizes, int n_in,
                              void* d_out, int out_size)
{
    const float* x     = (const float*)d_in[0];
    const void*  ei    = d_in[1];
    const float* ea    = (const float*)d_in[2];
    const float* W_em  = (const float*)d_in[3];
    const float* b_em  = (const float*)d_in[4];
    const float* W0    = (const float*)d_in[5];
    const float* b0    = (const float*)d_in[6];
    const float* Wl1   = (const float*)d_in[7];
    const float* bl1   = (const float*)d_in[8];
    const float* Wr1   = (const float*)d_in[9];
    const float* br1   = (const float*)d_in[10];
    const float* We1   = (const float*)d_in[11];
    const float* att1  = (const float*)d_in[12];
    const float* bias1 = (const float*)d_in[13];
    const float* Wl2   = (const float*)d_in[14];
    const float* bl2   = (const float*)d_in[15];
    const float* Wr2   = (const float*)d_in[16];
    const float* br2   = (const float*)d_in[17];
    const float* We2   = (const float*)d_in[18];
    const float* att2  = (const float*)d_in[19];
    const float* bias2 = (const float*)d_in[20];
    const float* Wd    = (const float*)d_in[21];
    const float* bd    = (const float*)d_in[22];
    float* out = (float*)d_out;

    int N = in_sizes[0];
    int E = in_sizes[2];
    int Eh = (E + 1) / 2;

    k_prez<<<(N + 255) / 256, 256>>>(W_em, b_em, W0, b0, Wl1, bl1, Wr1, br1, We1, We2, ei, N);
    k_convert<<<(Eh + 255) / 256, 256>>>(ei, E);
    k_scan1b<<<1, 1024>>>(N);
    k_scatter<<<(Eh + 255) / 256, 256>>>(ea, E);
    k_layer12<<<(N + 63) / 64, 256>>>(x, att1, bias1, Wl2, bl2, Wr2, br2, N);
    k_attn2<<<(N + 7) / 8, 256>>>(att2, bias2, Wd, N);
    k_final<<<(Eh + 255) / 256, 256>>>(bd, out, E);
}

// round 11
// speedup vs baseline: 1.2382x; 1.2382x over previous
#include <cuda_runtime.h>
#include <cuda_bf16.h>
#include <math.h>

#define MAXN 50000
#define MAXE 800000
#define SCAN_TILE 4096
#define MAX_BLKS ((MAXN + SCAN_TILE - 1) / SCAN_TILE + 1)

// ---------------- scratch (device globals; no allocation allowed) ----------------
__device__ int   g_is64;
__device__ __align__(16) int2  g_sd[MAXE];   // (src, dst) original order
__device__ int   g_rowptr[MAXN + 1];
__device__ int   g_cursor[MAXN];
__device__ int2  g_pair[MAXE];               // (src, ea-bits) sorted by dst
__device__ int   g_bsum[MAX_BLKS];
__device__ __align__(16) float g_xl2[(size_t)MAXN * 128];
__device__ __align__(16) float g_xr2[(size_t)MAXN * 128];
__device__ float g_p[MAXN];
__device__ float g_q[MAXN];
__device__ __align__(16) float4 g_cpack[64];
__device__ float g_aggA[64];
__device__ float g_aggC[64];
__device__ float g_u2[128];
__device__ float g_v2[128];

// ---------------- precompute + int64 detect + cursor zero (fused) ----------------
__global__ void k_prez(const float* __restrict__ W_em, const float* __restrict__ b_em,
                       const float* __restrict__ W0,   const float* __restrict__ b0,
                       const float* __restrict__ Wl1,  const float* __restrict__ bl1,
                       const float* __restrict__ Wr1,  const float* __restrict__ br1,
                       const float* __restrict__ We1,  const float* __restrict__ We2,
                       const void* __restrict__ ei, int N)
{
    int i = blockIdx.x * blockDim.x + threadIdx.x;
    if (i < N) g_cursor[i] = 0;
    if (blockIdx.x != 0) return;
    int t = threadIdx.x;
    if (t == 0) {
        const long long* p = (const long long*)ei;
        int is64 = 1;
        for (int k = 0; k < 8; k++) {
            long long v = p[k];
            if (v < 0 || v >= (1LL << 31)) { is64 = 0; break; }
        }
        g_is64 = is64;
    }
    if (t < 64) {
        float cS = 0.f, cD = 0.f, cE = 0.f;
        float Cl = bl1[t], Cr = br1[t], v1 = 0.f;
        for (int k = 0; k < 128; k++) {
            float wl = Wl1[k * 64 + t];
            float wr = Wr1[k * 64 + t];
            float we = We1[k * 64 + t];
            cS += W0[k]   * wl;
            cD += W0[k]   * wr;
            cE += W_em[k] * we;
            Cl += b0[k]   * wl;
            Cr += b0[k]   * wr;
            v1 += b_em[k] * we;
        }
        g_cpack[t] = make_float4(cS, cD, cE, Cl + Cr + v1);
        g_aggA[t] = cS;
        g_aggC[t] = Cl;
    }
    if (t >= 128 && t < 256) {
        int c = t - 128;
        float u = 0.f, v = 0.f;
        for (int k = 0; k < 128; k++) {
            float w = We2[k * 128 + c];
            u += W_em[k] * w;
            v += b_em[k] * w;
        }
        g_u2[c] = u;
        g_v2[c] = v;
    }
}

// ---------------- CSR build: 2 edges per thread ----------------
__global__ void k_convert(const void* __restrict__ ei, int E) {
    int t = blockIdx.x * blockDim.x + threadIdx.x;
    int e = 2 * t;
    if (e >= E) return;
    bool two = (e + 1 < E);
    int evenE = !(E & 1);
    int s0, d0, s1 = 0, d1 = 0;
    if (g_is64) {
        const long long* p = (const long long*)ei;
        longlong2 sv = ((const longlong2*)p)[t];
        s0 = (int)sv.x;
        if (two) s1 = (int)sv.y;
        if (evenE) {
            longlong2 dv = ((const longlong2*)(p + E))[t];
            d0 = (int)dv.x;
            if (two) d1 = (int)dv.y;
        } else {
            d0 = (int)p[E + e];
            if (two) d1 = (int)p[E + e + 1];
        }
    } else {
        const int* p = (const int*)ei;
        int2 sv = ((const int2*)p)[t];
        s0 = sv.x;
        if (two) s1 = sv.y;
        if (evenE) {
            int2 dv = ((const int2*)(p + E))[t];
            d0 = dv.x;
            if (two) d1 = dv.y;
        } else {
            d0 = p[E + e];
            if (two) d1 = p[E + e + 1];
        }
    }
    if (two) {
        ((int4*)g_sd)[t] = make_int4(s0, d0, s1, d1);
        atomicAdd(&g_cursor[d0], 1);
        atomicAdd(&g_cursor[d1], 1);
    } else {
        g_sd[e] = make_int2(s0, d0);
        atomicAdd(&g_cursor[d0], 1);
    }
}

// ---------------- parallel scan (R9 two-kernel version) ----------------
__global__ void k_bsum(int n) {
    __shared__ int ws[32];
    int tid = threadIdx.x;                       // 1024
    int base = blockIdx.x * SCAN_TILE;
    int sum = 0;
    #pragma unroll
    for (int k = 0; k < 4; k++) {
        int i = base + tid + k * 1024;
        if (i < n) sum += g_cursor[i];
    }
    int lane = tid & 31, w = tid >> 5;
    #pragma unroll
    for (int off = 16; off; off >>= 1) sum += __shfl_xor_sync(0xffffffffu, sum, off);
    if (lane == 0) ws[w] = sum;
    __syncthreads();
    if (w == 0) {
        int v = ws[lane];
        #pragma unroll
        for (int off = 16; off; off >>= 1) v += __shfl_xor_sync(0xffffffffu, v, off);
        if (lane == 0) g_bsum[blockIdx.x] = v;
    }
}

__global__ void k_scan2(int n, int nb) {
    __shared__ int s[SCAN_TILE];
    __shared__ int ws[32];
    __shared__ int s_boff;
    int tid = threadIdx.x;                        // 1024
    int base = blockIdx.x * SCAN_TILE;
    if (tid < 32) {
        int v = (tid < nb && tid < blockIdx.x) ? g_bsum[tid] : 0;
        #pragma unroll
        for (int off = 16; off; off >>= 1) v += __shfl_xor_sync(0xffffffffu, v, off);
        if (tid == 0) s_boff = v;
    }
    #pragma unroll
    for (int k = 0; k < 4; k++) {
        int i = base + tid + k * 1024;
        s[tid + k * 1024] = (i < n) ? g_cursor[i] : 0;
    }
    __syncthreads();
    int a0 = s[4 * tid], a1 = s[4 * tid + 1], a2 = s[4 * tid + 2], a3 = s[4 * tid + 3];
    int tsum = a0 + a1 + a2 + a3;
    int lane = tid & 31, w = tid >> 5;
    int incl = tsum;
    #pragma unroll
    for (int off = 1; off < 32; off <<= 1) {
        int t = __shfl_up_sync(0xffffffffu, incl, off);
        if (lane >= off) incl += t;
    }
    if (lane == 31) ws[w] = incl;
    __syncthreads();
    if (w == 0) {
        int y = ws[lane];
        #pragma unroll
        for (int off = 1; off < 32; off <<= 1) {
            int t = __shfl_up_sync(0xffffffffu, y, off);
            if (lane >= off) y += t;
        }
        ws[lane] = y;
    }
    __syncthreads();
    int run = s_boff + incl - tsum + (w > 0 ? ws[w - 1] : 0);
    int pref[4] = {run, run + a0, run + a0 + a1, run + a0 + a1 + a2};
    int av[4] = {a0, a1, a2, a3};
    #pragma unroll
    for (int k = 0; k < 4; k++) {
        int i = base + 4 * tid + k;
        if (i < n) { g_rowptr[i] = pref[k]; g_cursor[i] = pref[k]; }
        if (i == n - 1) g_rowptr[n] = pref[k] + av[k];
    }
}

// ---------------- scatter: 4 edges per thread (raise MLP on latency-bound atomics) ----------------
__global__ void k_scatter(const float* __restrict__ ea, int E) {
    int t = blockIdx.x * blockDim.x + threadIdx.x;
    int e = 4 * t;
    if (e >= E) return;
    if (e + 4 <= E) {
        int4 sdA = ((const int4*)g_sd)[2 * t];       // edges e, e+1
        int4 sdB = ((const int4*)g_sd)[2 * t + 1];   // edges e+2, e+3
        float4 av = ((const float4*)ea)[t];
        int pos0 = atomicAdd(&g_cursor[sdA.y], 1);
        int pos1 = atomicAdd(&g_cursor[sdA.w], 1);
        int pos2 = atomicAdd(&g_cursor[sdB.y], 1);
        int pos3 = atomicAdd(&g_cursor[sdB.w], 1);
        g_pair[pos0] = make_int2(sdA.x, __float_as_int(av.x));
        g_pair[pos1] = make_int2(sdA.z, __float_as_int(av.y));
        g_pair[pos2] = make_int2(sdB.x, __float_as_int(av.z));
        g_pair[pos3] = make_int2(sdB.z, __float_as_int(av.w));
    } else {
        for (int j = e; j < E; j++) {
            int2 sd = g_sd[j];
            int pos = atomicAdd(&g_cursor[sd.y], 1);
            g_pair[pos] = make_int2(sd.x, __float_as_int(ea[j]));
        }
    }
}

// ---------------- fused layer1 + lin2: 64-node tile per block, h1 in smem (R9 full-warp) ----------------
__global__ void k_layer12(const float* __restrict__ x,
                          const float* __restrict__ att1, const float* __restrict__ bias1,
                          const float* __restrict__ Wl, const float* __restrict__ bl,
                          const float* __restrict__ Wr, const float* __restrict__ br,
                          int N)
{
    __shared__ float4 sc[64];
    __shared__ float  sa[64];
    __shared__ float  sb1[64];
    __shared__ float  sH[64 * 64];       // h1 tile, 16 KB
    int tid = threadIdx.x;               // 256
    if (tid < 64) { sc[tid] = g_cpack[tid]; sa[tid] = att1[tid]; sb1[tid] = bias1[tid]; }
    __syncthreads();
    int warp = tid >> 5, lane = tid & 31;
    int tile0 = blockIdx.x * 64;

    // ---- phase 1: layer-1 attention, 8 nodes per warp (sequential) ----
    for (int r = 0; r < 8; r++) {
        int n = tile0 + warp * 8 + r;
        int nl = warp * 8 + r;
        if (n >= N) break;
        int beg = g_rowptr[n], end = g_rowptr[n + 1];
        float xd = x[n];

        float mx[8], den[8], s1[8];
        #pragma unroll
        for (int h = 0; h < 8; h++) { mx[h] = -1e30f; den[h] = 0.f; s1[h] = 0.f; }

        int eix = beg + lane;
        for (; eix + 32 < end; eix += 64) {
            int2 p0 = g_pair[eix], p1 = g_pair[eix + 32];
            float xs0 = x[p0.x], xs1 = x[p1.x];
            float a0 = __int_as_float(p0.y), a1 = __int_as_float(p1.y);
            #pragma unroll
            for (int h = 0; h < 8; h++) {
                float v0 = 0.f, v1 = 0.f;
                #pragma unroll
                for (int c = 0; c < 8; c++) {
                    int j = h * 8 + c;
                    float4 q = sc[j];
                    float m0 = fmaf(q.x, xs0, fmaf(q.y, xd, fmaf(q.z, a0, q.w)));
                    float m1 = fmaf(q.x, xs1, fmaf(q.y, xd, fmaf(q.z, a1, q.w)));
                    m0 = m0 > 0.f ? m0 : 0.2f * m0;
                    m1 = m1 > 0.f ? m1 : 0.2f * m1;
                    v0 = fmaf(m0, sa[j], v0);
                    v1 = fmaf(m1, sa[j], v1);
                }
                float mb = fmaxf(v0, v1);
                float e0 = __expf(v0 - mb), e1 = __expf(v1 - mb);
                float mnew = fmaxf(mx[h], mb);
                float corr  = __expf(mx[h] - mnew);
                float scale = __expf(mb - mnew);
                den[h] = fmaf(den[h], corr, (e0 + e1) * scale);
                s1[h]  = fmaf(s1[h],  corr, fmaf(e0, xs0, e1 * xs1) * scale);
                mx[h] = mnew;
            }
        }
        if (eix < end) {
            int2 pr = g_pair[eix];
            float xs = x[pr.x];
            float a  = __int_as_float(pr.y);
            #pragma unroll
            for (int h = 0; h < 8; h++) {
                float scv = 0.f;
                #pragma unroll
                for (int c = 0; c < 8; c++) {
                    int j = h * 8 + c;
                    float4 q = sc[j];
                    float m = fmaf(q.x, xs, fmaf(q.y, xd, fmaf(q.z, a, q.w)));
                    m = m > 0.f ? m : 0.2f * m;
                    scv = fmaf(m, sa[j], scv);
                }
                float mnew = fmaxf(mx[h], scv);
                float corr = __expf(mx[h] - mnew);
                float ex   = __expf(scv - mnew);
                den[h] = fmaf(den[h], corr, ex);
                s1[h]  = fmaf(s1[h],  corr, ex * xs);
                mx[h] = mnew;
            }
        }
        #pragma unroll
        for (int h = 0; h < 8; h++) {
            float M = mx[h];
            #pragma unroll
            for (int off = 16; off; off >>= 1)
                M = fmaxf(M, __shfl_xor_sync(0xffffffffu, M, off));
            float corr = __expf(mx[h] - M);
            float d2 = den[h] * corr;
            float s2 = s1[h]  * corr;
            #pragma unroll
            for (int off = 16; off; off >>= 1) {
                d2 += __shfl_xor_sync(0xffffffffu, d2, off);
                s2 += __shfl_xor_sync(0xffffffffu, s2, off);
            }
            den[h] = d2; s1[h] = s2;
        }

        float s0 = (end > beg) ? 1.f : 0.f;
        #pragma unroll
        for (int rr = 0; rr < 2; rr++) {
            int j = lane + rr * 32;
            int h = j >> 3;
            float S1 = s1[h] / fmaxf(den[h], 1e-16f);
            float o = fmaf(g_aggA[j], S1, fmaf(g_aggC[j], s0, sb1[j]));
            o = o > 0.f ? o : expm1f(o);    // elu
            sH[nl * 64 + j] = o;
        }
    }
    __syncthreads();

    // ---- phase 2: two GEMVs from smem h1 ----
    int half = tid >> 7;                   // 0 -> xl2, 1 -> xr2
    int col  = tid & 127;
    const float* W = half ? Wr : Wl;
    const float* b = half ? br : bl;
    float* out = half ? g_xr2 : g_xl2;

    float wcol[64];
    float bb = b[col];
    #pragma unroll
    for (int k = 0; k < 64; k++) wcol[k] = W[k * 128 + col];

    int rows = min(64, N - tile0);
    for (int r = 0; r < rows; r++) {
        const float4* rv4 = (const float4*)&sH[r * 64];
        float acc = bb;
        #pragma unroll
        for (int k4 = 0; k4 < 16; k4++) {
            float4 rv = rv4[k4];
            acc = fmaf(rv.x, wcol[4 * k4 + 0], acc);
            acc = fmaf(rv.y, wcol[4 * k4 + 1], acc);
            acc = fmaf(rv.z, wcol[4 * k4 + 2], acc);
            acc = fmaf(rv.w, wcol[4 * k4 + 3], acc);
        }
        out[(size_t)(tile0 + r) * 128 + col] = acc;
    }
}

// ---------------- layer 2 attention: float4 channels, batch-4 online softmax ----------------
__global__ void k_attn2(const float* __restrict__ att2,
                        const float* __restrict__ bias2, const float* __restrict__ Wd,
                        int N)
{
    __shared__ float su[128], sv[128], sat[128], sb2[128], swd[256];
    int tid = threadIdx.x;  // 256
    if (tid < 128) { su[tid] = g_u2[tid]; sv[tid] = g_v2[tid]; sat[tid] = att2[tid]; sb2[tid] = bias2[tid]; }
    if (tid < 256) swd[tid] = Wd[tid];
    __syncthreads();
    int warp = tid >> 5, lane = tid & 31;
    int n = blockIdx.x * 8 + warp;
    if (n >= N) return;
    int beg = g_rowptr[n], end = g_rowptr[n + 1];

    float4 xr = ((const float4*)(&g_xr2[(size_t)n * 128]))[lane];
    float u[4], v[4], at[4];
    #pragma unroll
    for (int k = 0; k < 4; k++) {
        int ch = 4 * lane + k;
        u[k] = su[ch]; v[k] = sv[ch]; at[k] = sat[ch];
    }
    float xrv[4] = {xr.x, xr.y, xr.z, xr.w};

    float mx = -1e30f, den = 0.f;
    float acc[4] = {0.f, 0.f, 0.f, 0.f};

    int ei = beg;
    for (; ei + 4 <= end; ei += 4) {
        float sc[4];
        float4 xlv[4];
        #pragma unroll
        for (int j = 0; j < 4; j++) {
            int2 pr = g_pair[ei + j];
            xlv[j] = ((const float4*)(&g_xl2[(size_t)pr.x * 128]))[lane];
            float a = __int_as_float(pr.y);
            const float* xv = (const float*)&xlv[j];
            float t = 0.f;
            #pragma unroll
            for (int k = 0; k < 4; k++) {
                float m = xv[k] + xrv[k] + fmaf(a, u[k], v[k]);
                m = m > 0.f ? m : 0.2f * m;
                t = fmaf(m, at[k], t);
            }
            sc[j] = t;
        }
        #pragma unroll
        for (int off = 16; off; off >>= 1) {
            #pragma unroll
            for (int j = 0; j < 4; j++)
                sc[j] += __shfl_xor_sync(0xffffffffu, sc[j], off);
        }
        float mb = fmaxf(fmaxf(sc[0], sc[1]), fmaxf(sc[2], sc[3]));
        float ex0 = __expf(sc[0] - mb), ex1 = __expf(sc[1] - mb);
        float ex2 = __expf(sc[2] - mb), ex3 = __expf(sc[3] - mb);
        float mnew = fmaxf(mx, mb);
        float corr  = __expf(mx - mnew);
        float scale = __expf(mb - mnew);
        den = fmaf(den, corr, (ex0 + ex1 + ex2 + ex3) * scale);
        #pragma unroll
        for (int k = 0; k < 4; k++) {
            float s = fmaf(ex0, ((const float*)&xlv[0])[k],
                      fmaf(ex1, ((const float*)&xlv[1])[k],
                      fmaf(ex2, ((const float*)&xlv[2])[k],
                           ex3 * ((const float*)&xlv[3])[k])));
            acc[k] = fmaf(acc[k], corr, s * scale);
        }
        mx = mnew;
    }
    for (; ei < end; ei++) {
        int2 pr = g_pair[ei];
        float4 xl4 = ((const float4*)(&g_xl2[(size_t)pr.x * 128]))[lane];
        const float* xv = (const float*)&xl4;
        float a = __int_as_float(pr.y);
        float sc = 0.f;
        #pragma unroll
        for (int k = 0; k < 4; k++) {
            float m = xv[k] + xrv[k] + fmaf(a, u[k], v[k]);
            m = m > 0.f ? m : 0.2f * m;
            sc = fmaf(m, at[k], sc);
        }
        #pragma unroll
        for (int off = 16; off; off >>= 1) sc += __shfl_xor_sync(0xffffffffu, sc, off);
        float mnew = fmaxf(mx, sc);
        float corr = __expf(mx - mnew);
        float ex   = __expf(sc - mnew);
        den = fmaf(den, corr, ex);
        #pragma unroll
        for (int k = 0; k < 4; k++) acc[k] = fmaf(acc[k], corr, ex * xv[k]);
        mx = mnew;
    }
    den = fmaxf(den, 1e-16f);

    float p = 0.f, q = 0.f;
    #pragma unroll
    for (int k = 0; k < 4; k++) {
        int ch = 4 * lane + k;
        float h2 = acc[k] / den + sb2[ch];
        p = fmaf(h2, swd[ch], p);
        q = fmaf(h2, swd[128 + ch], q);
    }
    #pragma unroll
    for (int off = 16; off; off >>= 1) {
        p += __shfl_xor_sync(0xffffffffu, p, off);
        q += __shfl_xor_sync(0xffffffffu, q, off);
    }
    if (lane == 0) { g_p[n] = p; g_q[n] = q; }
}

// ---------------- final edge output: 2 edges per thread ----------------
__global__ void k_final(const float* __restrict__ bd, float* __restrict__ out, int E) {
    int t = blockIdx.x * blockDim.x + threadIdx.x;
    int e = 2 * t;
    if (e >= E) return;
    float b = bd[0];
    if (e + 1 < E) {
        int4 sd2 = ((const int4*)g_sd)[t];
        float2 o;
        o.x = g_p[sd2.x] + g_q[sd2.y] + b;
        o.y = g_p[sd2.z] + g_q[sd2.w] + b;
        ((float2*)out)[t] = o;
    } else {
        int2 sd = g_sd[e];
        out[e] = g_p[sd.x] + g_q[sd.y] + b;
    }
}

// ---------------- launch ----------------
extern "C" void kernel_launch(void* const* d_in, const int* in_sizes, int n_in,
                              void* d_out, int out_size)
{
    const float* x     = (const float*)d_in[0];
    const void*  ei    = d_in[1];
    const float* ea    = (const float*)d_in[2];
    const float* W_em  = (const float*)d_in[3];
    const float* b_em  = (const float*)d_in[4];
    const float* W0    = (const float*)d_in[5];
    const float* b0    = (const float*)d_in[6];
    const float* Wl1   = (const float*)d_in[7];
    const float* bl1   = (const float*)d_in[8];
    const float* Wr1   = (const float*)d_in[9];
    const float* br1   = (const float*)d_in[10];
    const float* We1   = (const float*)d_in[11];
    const float* att1  = (const float*)d_in[12];
    const float* bias1 = (const float*)d_in[13];
    const float* Wl2   = (const float*)d_in[14];
    const float* bl2   = (const float*)d_in[15];
    const float* Wr2   = (const float*)d_in[16];
    const float* br2   = (const float*)d_in[17];
    const float* We2   = (const float*)d_in[18];
    const float* att2  = (const float*)d_in[19];
    const float* bias2 = (const float*)d_in[20];
    const float* Wd    = (const float*)d_in[21];
    const float* bd    = (const float*)d_in[22];
    float* out = (float*)d_out;

    int N = in_sizes[0];
    int E = in_sizes[2];
    int NB = (N + SCAN_TILE - 1) / SCAN_TILE;
    int Eh = (E + 1) / 2;
    int Eq = (E + 3) / 4;

    k_prez<<<(N + 255) / 256, 256>>>(W_em, b_em, W0, b0, Wl1, bl1, Wr1, br1, We1, We2, ei, N);
    k_convert<<<(Eh + 255) / 256, 256>>>(ei, E);
    k_bsum<<<NB, 1024>>>(N);
    k_scan2<<<NB, 1024>>>(N, NB);
    k_scatter<<<(Eq + 255) / 256, 256>>>(ea, E);
    k_layer12<<<(N + 63) / 64, 256>>>(x, att1, bias1, Wl2, bl2, Wr2, br2, N);
    k_attn2<<<(N + 7) / 8, 256>>>(att2, bias2, Wd, N);
    k_final<<<(Eh + 255) / 256, 256>>>(bd, out, E);
}

// round 12
// speedup vs baseline: 1.3521x; 1.0920x over previous
#include <cuda_runtime.h>
#include <cuda_bf16.h>
#include <cuda_fp16.h>
#include <math.h>

#define MAXN 50000
#define MAXE 800000
#define SCAN_TILE 4096
#define MAX_BLKS ((MAXN + SCAN_TILE - 1) / SCAN_TILE + 1)

// ---------------- scratch (device globals; no allocation allowed) ----------------
__device__ int   g_is64;
__device__ __align__(16) int2  g_sd[MAXE];   // (src, dst) original order
__device__ int   g_rowptr[MAXN + 1];
__device__ int   g_cursor[MAXN];
__device__ int2  g_pair[MAXE];               // (src, ea-bits) sorted by dst
__device__ int   g_bsum[MAX_BLKS];
__device__ __align__(16) __half g_xl2h[(size_t)MAXN * 128];  // fp16 score operand
__device__ __align__(16) float  g_xr2[(size_t)MAXN * 128];
__device__ __align__(16) float2 g_pq[MAXN];  // (P, Q) per-node projection scalars
__device__ float g_p[MAXN];
__device__ float g_q[MAXN];
__device__ __align__(16) float4 g_cpack[64];
__device__ float g_aggA[64];
__device__ float g_aggC[64];
__device__ float g_u2[128];
__device__ float g_v2[128];
__device__ float g_wP[64];     // Wl2 @ Wd[:128]
__device__ float g_wQ[64];     // Wl2 @ Wd[128:]
__device__ float g_cP, g_cQ;   // bl2 @ Wd halves
__device__ float g_cB1, g_cB2; // bias2 @ Wd halves

// ---------------- precompute + int64 detect + cursor zero (fused) ----------------
__global__ void k_prez(const float* __restrict__ W_em, const float* __restrict__ b_em,
                       const float* __restrict__ W0,   const float* __restrict__ b0,
                       const float* __restrict__ Wl1,  const float* __restrict__ bl1,
                       const float* __restrict__ Wr1,  const float* __restrict__ br1,
                       const float* __restrict__ We1,  const float* __restrict__ We2,
                       const float* __restrict__ Wl2,  const float* __restrict__ bl2,
                       const float* __restrict__ bias2,const float* __restrict__ Wd,
                       const void* __restrict__ ei, int N)
{
    int i = blockIdx.x * blockDim.x + threadIdx.x;
    if (i < N) g_cursor[i] = 0;
    if (blockIdx.x != 0) return;
    int t = threadIdx.x;
    if (t == 0) {
        const long long* p = (const long long*)ei;
        int is64 = 1;
        for (int k = 0; k < 8; k++) {
            long long v = p[k];
            if (v < 0 || v >= (1LL << 31)) { is64 = 0; break; }
        }
        g_is64 = is64;
    }
    if (t == 1) {
        float cP = 0.f, cQ = 0.f, c1 = 0.f, c2 = 0.f;
        for (int j = 0; j < 128; j++) {
            cP += bl2[j]   * Wd[j];
            cQ += bl2[j]   * Wd[128 + j];
            c1 += bias2[j] * Wd[j];
            c2 += bias2[j] * Wd[128 + j];
        }
        g_cP = cP; g_cQ = cQ; g_cB1 = c1; g_cB2 = c2;
    }
    if (t < 64) {
        float cS = 0.f, cD = 0.f, cE = 0.f;
        float Cl = bl1[t], Cr = br1[t], v1 = 0.f;
        for (int k = 0; k < 128; k++) {
            float wl = Wl1[k * 64 + t];
            float wr = Wr1[k * 64 + t];
            float we = We1[k * 64 + t];
            cS += W0[k]   * wl;
            cD += W0[k]   * wr;
            cE += W_em[k] * we;
            Cl += b0[k]   * wl;
            Cr += b0[k]   * wr;
            v1 += b_em[k] * we;
        }
        g_cpack[t] = make_float4(cS, cD, cE, Cl + Cr + v1);
        g_aggA[t] = cS;
        g_aggC[t] = Cl;
        // wP/wQ folds: Wl2[k, :] . Wd halves
        float wp = 0.f, wq = 0.f;
        for (int j = 0; j < 128; j++) {
            float w = Wl2[t * 128 + j];
            wp += w * Wd[j];
            wq += w * Wd[128 + j];
        }
        g_wP[t] = wp;
        g_wQ[t] = wq;
    }
    if (t >= 128 && t < 256) {
        int c = t - 128;
        float u = 0.f, v = 0.f;
        for (int k = 0; k < 128; k++) {
            float w = We2[k * 128 + c];
            u += W_em[k] * w;
            v += b_em[k] * w;
        }
        g_u2[c] = u;
        g_v2[c] = v;
    }
}

// ---------------- CSR build: 2 edges per thread ----------------
__global__ void k_convert(const void* __restrict__ ei, int E) {
    int t = blockIdx.x * blockDim.x + threadIdx.x;
    int e = 2 * t;
    if (e >= E) return;
    bool two = (e + 1 < E);
    int evenE = !(E & 1);
    int s0, d0, s1 = 0, d1 = 0;
    if (g_is64) {
        const long long* p = (const long long*)ei;
        longlong2 sv = ((const longlong2*)p)[t];
        s0 = (int)sv.x;
        if (two) s1 = (int)sv.y;
        if (evenE) {
            longlong2 dv = ((const longlong2*)(p + E))[t];
            d0 = (int)dv.x;
            if (two) d1 = (int)dv.y;
        } else {
            d0 = (int)p[E + e];
            if (two) d1 = (int)p[E + e + 1];
        }
    } else {
        const int* p = (const int*)ei;
        int2 sv = ((const int2*)p)[t];
        s0 = sv.x;
        if (two) s1 = sv.y;
        if (evenE) {
            int2 dv = ((const int2*)(p + E))[t];
            d0 = dv.x;
            if (two) d1 = dv.y;
        } else {
            d0 = p[E + e];
            if (two) d1 = p[E + e + 1];
        }
    }
    if (two) {
        ((int4*)g_sd)[t] = make_int4(s0, d0, s1, d1);
        atomicAdd(&g_cursor[d0], 1);
        atomicAdd(&g_cursor[d1], 1);
    } else {
        g_sd[e] = make_int2(s0, d0);
        atomicAdd(&g_cursor[d0], 1);
    }
}

// ---------------- parallel scan ----------------
__global__ void k_bsum(int n) {
    __shared__ int ws[32];
    int tid = threadIdx.x;                       // 1024
    int base = blockIdx.x * SCAN_TILE;
    int sum = 0;
    #pragma unroll
    for (int k = 0; k < 4; k++) {
        int i = base + tid + k * 1024;
        if (i < n) sum += g_cursor[i];
    }
    int lane = tid & 31, w = tid >> 5;
    #pragma unroll
    for (int off = 16; off; off >>= 1) sum += __shfl_xor_sync(0xffffffffu, sum, off);
    if (lane == 0) ws[w] = sum;
    __syncthreads();
    if (w == 0) {
        int v = ws[lane];
        #pragma unroll
        for (int off = 16; off; off >>= 1) v += __shfl_xor_sync(0xffffffffu, v, off);
        if (lane == 0) g_bsum[blockIdx.x] = v;
    }
}

__global__ void k_scan2(int n, int nb) {
    __shared__ int s[SCAN_TILE];
    __shared__ int ws[32];
    __shared__ int s_boff;
    int tid = threadIdx.x;                        // 1024
    int base = blockIdx.x * SCAN_TILE;
    if (tid < 32) {
        int v = (tid < nb && tid < blockIdx.x) ? g_bsum[tid] : 0;
        #pragma unroll
        for (int off = 16; off; off >>= 1) v += __shfl_xor_sync(0xffffffffu, v, off);
        if (tid == 0) s_boff = v;
    }
    #pragma unroll
    for (int k = 0; k < 4; k++) {
        int i = base + tid + k * 1024;
        s[tid + k * 1024] = (i < n) ? g_cursor[i] : 0;
    }
    __syncthreads();
    int a0 = s[4 * tid], a1 = s[4 * tid + 1], a2 = s[4 * tid + 2], a3 = s[4 * tid + 3];
    int tsum = a0 + a1 + a2 + a3;
    int lane = tid & 31, w = tid >> 5;
    int incl = tsum;
    #pragma unroll
    for (int off = 1; off < 32; off <<= 1) {
        int t = __shfl_up_sync(0xffffffffu, incl, off);
        if (lane >= off) incl += t;
    }
    if (lane == 31) ws[w] = incl;
    __syncthreads();
    if (w == 0) {
        int y = ws[lane];
        #pragma unroll
        for (int off = 1; off < 32; off <<= 1) {
            int t = __shfl_up_sync(0xffffffffu, y, off);
            if (lane >= off) y += t;
        }
        ws[lane] = y;
    }
    __syncthreads();
    int run = s_boff + incl - tsum + (w > 0 ? ws[w - 1] : 0);
    int pref[4] = {run, run + a0, run + a0 + a1, run + a0 + a1 + a2};
    int av[4] = {a0, a1, a2, a3};
    #pragma unroll
    for (int k = 0; k < 4; k++) {
        int i = base + 4 * tid + k;
        if (i < n) { g_rowptr[i] = pref[k]; g_cursor[i] = pref[k]; }
        if (i == n - 1) g_rowptr[n] = pref[k] + av[k];
    }
}

// ---------------- scatter: 4 edges per thread ----------------
__global__ void k_scatter(const float* __restrict__ ea, int E) {
    int t = blockIdx.x * blockDim.x + threadIdx.x;
    int e = 4 * t;
    if (e >= E) return;
    if (e + 4 <= E) {
        int4 sdA = ((const int4*)g_sd)[2 * t];
        int4 sdB = ((const int4*)g_sd)[2 * t + 1];
        float4 av = ((const float4*)ea)[t];
        int pos0 = atomicAdd(&g_cursor[sdA.y], 1);
        int pos1 = atomicAdd(&g_cursor[sdA.w], 1);
        int pos2 = atomicAdd(&g_cursor[sdB.y], 1);
        int pos3 = atomicAdd(&g_cursor[sdB.w], 1);
        g_pair[pos0] = make_int2(sdA.x, __float_as_int(av.x));
        g_pair[pos1] = make_int2(sdA.z, __float_as_int(av.y));
        g_pair[pos2] = make_int2(sdB.x, __float_as_int(av.z));
        g_pair[pos3] = make_int2(sdB.z, __float_as_int(av.w));
    } else {
        for (int j = e; j < E; j++) {
            int2 sd = g_sd[j];
            int pos = atomicAdd(&g_cursor[sd.y], 1);
            g_pair[pos] = make_int2(sd.x, __float_as_int(ea[j]));
        }
    }
}

// ---------------- fused layer1 + lin2 + PQ scalars ----------------
__global__ void k_layer12(const float* __restrict__ x,
                          const float* __restrict__ att1, const float* __restrict__ bias1,
                          const float* __restrict__ Wl, const float* __restrict__ bl,
                          const float* __restrict__ Wr, const float* __restrict__ br,
                          int N)
{
    __shared__ float4 sc[64];
    __shared__ float  sa[64];
    __shared__ float  sb1[64];
    __shared__ float  swP[64], swQ[64];
    __shared__ float  sH[64 * 64];       // h1 tile, 16 KB
    int tid = threadIdx.x;               // 256
    if (tid < 64) {
        sc[tid] = g_cpack[tid]; sa[tid] = att1[tid]; sb1[tid] = bias1[tid];
        swP[tid] = g_wP[tid]; swQ[tid] = g_wQ[tid];
    }
    __syncthreads();
    int warp = tid >> 5, lane = tid & 31;
    int tile0 = blockIdx.x * 64;

    // ---- phase 1: layer-1 attention, 8 nodes per warp ----
    for (int r = 0; r < 8; r++) {
        int n = tile0 + warp * 8 + r;
        int nl = warp * 8 + r;
        if (n >= N) break;
        int beg = g_rowptr[n], end = g_rowptr[n + 1];
        float xd = x[n];

        float mx[8], den[8], s1[8];
        #pragma unroll
        for (int h = 0; h < 8; h++) { mx[h] = -1e30f; den[h] = 0.f; s1[h] = 0.f; }

        int eix = beg + lane;
        for (; eix + 32 < end; eix += 64) {
            int2 p0 = g_pair[eix], p1 = g_pair[eix + 32];
            float xs0 = x[p0.x], xs1 = x[p1.x];
            float a0 = __int_as_float(p0.y), a1 = __int_as_float(p1.y);
            #pragma unroll
            for (int h = 0; h < 8; h++) {
                float v0 = 0.f, v1 = 0.f;
                #pragma unroll
                for (int c = 0; c < 8; c++) {
                    int j = h * 8 + c;
                    float4 q = sc[j];
                    float m0 = fmaf(q.x, xs0, fmaf(q.y, xd, fmaf(q.z, a0, q.w)));
                    float m1 = fmaf(q.x, xs1, fmaf(q.y, xd, fmaf(q.z, a1, q.w)));
                    m0 = m0 > 0.f ? m0 : 0.2f * m0;
                    m1 = m1 > 0.f ? m1 : 0.2f * m1;
                    v0 = fmaf(m0, sa[j], v0);
                    v1 = fmaf(m1, sa[j], v1);
                }
                float mb = fmaxf(v0, v1);
                float e0 = __expf(v0 - mb), e1 = __expf(v1 - mb);
                float mnew = fmaxf(mx[h], mb);
                float corr  = __expf(mx[h] - mnew);
                float scale = __expf(mb - mnew);
                den[h] = fmaf(den[h], corr, (e0 + e1) * scale);
                s1[h]  = fmaf(s1[h],  corr, fmaf(e0, xs0, e1 * xs1) * scale);
                mx[h] = mnew;
            }
        }
        if (eix < end) {
            int2 pr = g_pair[eix];
            float xs = x[pr.x];
            float a  = __int_as_float(pr.y);
            #pragma unroll
            for (int h = 0; h < 8; h++) {
                float scv = 0.f;
                #pragma unroll
                for (int c = 0; c < 8; c++) {
                    int j = h * 8 + c;
                    float4 q = sc[j];
                    float m = fmaf(q.x, xs, fmaf(q.y, xd, fmaf(q.z, a, q.w)));
                    m = m > 0.f ? m : 0.2f * m;
                    scv = fmaf(m, sa[j], scv);
                }
                float mnew = fmaxf(mx[h], scv);
                float corr = __expf(mx[h] - mnew);
                float ex   = __expf(scv - mnew);
                den[h] = fmaf(den[h], corr, ex);
                s1[h]  = fmaf(s1[h],  corr, ex * xs);
                mx[h] = mnew;
            }
        }
        #pragma unroll
        for (int h = 0; h < 8; h++) {
            float M = mx[h];
            #pragma unroll
            for (int off = 16; off; off >>= 1)
                M = fmaxf(M, __shfl_xor_sync(0xffffffffu, M, off));
            float corr = __expf(mx[h] - M);
            float d2 = den[h] * corr;
            float s2 = s1[h]  * corr;
            #pragma unroll
            for (int off = 16; off; off >>= 1) {
                d2 += __shfl_xor_sync(0xffffffffu, d2, off);
                s2 += __shfl_xor_sync(0xffffffffu, s2, off);
            }
            den[h] = d2; s1[h] = s2;
        }

        float s0 = (end > beg) ? 1.f : 0.f;
        float o0, o1;
        {
            int j = lane, h = j >> 3;
            float S1 = s1[h] / fmaxf(den[h], 1e-16f);
            o0 = fmaf(g_aggA[j], S1, fmaf(g_aggC[j], s0, sb1[j]));
            o0 = o0 > 0.f ? o0 : expm1f(o0);
            sH[nl * 64 + j] = o0;
        }
        {
            int j = lane + 32, h = j >> 3;
            float S1 = s1[h] / fmaxf(den[h], 1e-16f);
            o1 = fmaf(g_aggA[j], S1, fmaf(g_aggC[j], s0, sb1[j]));
            o1 = o1 > 0.f ? o1 : expm1f(o1);
            sH[nl * 64 + j] = o1;
        }
        // P/Q projection scalars: P = h1 . wP + cP
        float pv = fmaf(o0, swP[lane], o1 * swP[lane + 32]);
        float qv = fmaf(o0, swQ[lane], o1 * swQ[lane + 32]);
        #pragma unroll
        for (int off = 16; off; off >>= 1) {
            pv += __shfl_xor_sync(0xffffffffu, pv, off);
            qv += __shfl_xor_sync(0xffffffffu, qv, off);
        }
        if (lane == 0) g_pq[n] = make_float2(pv + g_cP, qv + g_cQ);
    }
    __syncthreads();

    // ---- phase 2: two GEMVs from smem h1; xl side stored as fp16 ----
    int half = tid >> 7;                   // 0 -> xl2h (fp16), 1 -> xr2 (fp32)
    int col  = tid & 127;
    const float* W = half ? Wr : Wl;
    const float* b = half ? br : bl;

    float wcol[64];
    float bb = b[col];
    #pragma unroll
    for (int k = 0; k < 64; k++) wcol[k] = W[k * 128 + col];

    int rows = min(64, N - tile0);
    for (int r = 0; r < rows; r++) {
        const float4* rv4 = (const float4*)&sH[r * 64];
        float acc = bb;
        #pragma unroll
        for (int k4 = 0; k4 < 16; k4++) {
            float4 rv = rv4[k4];
            acc = fmaf(rv.x, wcol[4 * k4 + 0], acc);
            acc = fmaf(rv.y, wcol[4 * k4 + 1], acc);
            acc = fmaf(rv.z, wcol[4 * k4 + 2], acc);
            acc = fmaf(rv.w, wcol[4 * k4 + 3], acc);
        }
        size_t idx = (size_t)(tile0 + r) * 128 + col;
        if (half) g_xr2[idx] = acc;
        else      g_xl2h[idx] = __float2half(acc);
    }
}

// ---------------- layer 2 attention: fp16 scores + scalar P/Q accumulation ----------------
__global__ void k_attn2(const float* __restrict__ att2, int N)
{
    __shared__ float su[128], sv[128], sat[128];
    int tid = threadIdx.x;  // 256
    if (tid < 128) { su[tid] = g_u2[tid]; sv[tid] = g_v2[tid]; sat[tid] = att2[tid]; }
    __syncthreads();
    int warp = tid >> 5, lane = tid & 31;
    int n = blockIdx.x * 8 + warp;
    if (n >= N) return;
    int beg = g_rowptr[n], end = g_rowptr[n + 1];

    float4 xr = ((const float4*)(&g_xr2[(size_t)n * 128]))[lane];
    float u[4], v[4], at[4];
    #pragma unroll
    for (int k = 0; k < 4; k++) {
        int ch = 4 * lane + k;
        u[k] = su[ch]; v[k] = sv[ch]; at[k] = sat[ch];
    }
    float xrv[4] = {xr.x, xr.y, xr.z, xr.w};

    float mx = -1e30f, den = 0.f, accP = 0.f, accQ = 0.f;

    int ei = beg;
    for (; ei + 4 <= end; ei += 4) {
        float sc[4];
        float2 pq[4];
        #pragma unroll
        for (int j = 0; j < 4; j++) {
            int2 pr = g_pair[ei + j];
            uint2 hx = ((const uint2*)g_xl2h)[(size_t)pr.x * 32 + lane];
            pq[j] = g_pq[pr.x];
            float a = __int_as_float(pr.y);
            float2 lo = __half22float2(*(__half2*)&hx.x);
            float2 hi = __half22float2(*(__half2*)&hx.y);
            float xl[4] = {lo.x, lo.y, hi.x, hi.y};
            float t = 0.f;
            #pragma unroll
            for (int k = 0; k < 4; k++) {
                float m = xl[k] + xrv[k] + fmaf(a, u[k], v[k]);
                m = m > 0.f ? m : 0.2f * m;
                t = fmaf(m, at[k], t);
            }
            sc[j] = t;
        }
        #pragma unroll
        for (int off = 16; off; off >>= 1) {
            #pragma unroll
            for (int j = 0; j < 4; j++)
                sc[j] += __shfl_xor_sync(0xffffffffu, sc[j], off);
        }
        float mb = fmaxf(fmaxf(sc[0], sc[1]), fmaxf(sc[2], sc[3]));
        float ex0 = __expf(sc[0] - mb), ex1 = __expf(sc[1] - mb);
        float ex2 = __expf(sc[2] - mb), ex3 = __expf(sc[3] - mb);
        float mnew = fmaxf(mx, mb);
        float corr  = __expf(mx - mnew);
        float scale = __expf(mb - mnew);
        den  = fmaf(den,  corr, (ex0 + ex1 + ex2 + ex3) * scale);
        float sp = fmaf(ex0, pq[0].x, fmaf(ex1, pq[1].x, fmaf(ex2, pq[2].x, ex3 * pq[3].x)));
        float sq = fmaf(ex0, pq[0].y, fmaf(ex1, pq[1].y, fmaf(ex2, pq[2].y, ex3 * pq[3].y)));
        accP = fmaf(accP, corr, sp * scale);
        accQ = fmaf(accQ, corr, sq * scale);
        mx = mnew;
    }
    for (; ei < end; ei++) {
        int2 pr = g_pair[ei];
        uint2 hx = ((const uint2*)g_xl2h)[(size_t)pr.x * 32 + lane];
        float2 pqv = g_pq[pr.x];
        float a = __int_as_float(pr.y);
        float2 lo = __half22float2(*(__half2*)&hx.x);
        float2 hi = __half22float2(*(__half2*)&hx.y);
        float xl[4] = {lo.x, lo.y, hi.x, hi.y};
        float sc = 0.f;
        #pragma unroll
        for (int k = 0; k < 4; k++) {
            float m = xl[k] + xrv[k] + fmaf(a, u[k], v[k]);
            m = m > 0.f ? m : 0.2f * m;
            sc = fmaf(m, at[k], sc);
        }
        #pragma unroll
        for (int off = 16; off; off >>= 1) sc += __shfl_xor_sync(0xffffffffu, sc, off);
        float mnew = fmaxf(mx, sc);
        float corr = __expf(mx - mnew);
        float ex   = __expf(sc - mnew);
        den  = fmaf(den,  corr, ex);
        accP = fmaf(accP, corr, ex * pqv.x);
        accQ = fmaf(accQ, corr, ex * pqv.y);
        mx = mnew;
    }
    den = fmaxf(den, 1e-16f);
    if (lane == 0) {
        g_p[n] = accP / den + g_cB1;
        g_q[n] = accQ / den + g_cB2;
    }
}

// ---------------- final edge output: 2 edges per thread ----------------
__global__ void k_final(const float* __restrict__ bd, float* __restrict__ out, int E) {
    int t = blockIdx.x * blockDim.x + threadIdx.x;
    int e = 2 * t;
    if (e >= E) return;
    float b = bd[0];
    if (e + 1 < E) {
        int4 sd2 = ((const int4*)g_sd)[t];
        float2 o;
        o.x = g_p[sd2.x] + g_q[sd2.y] + b;
        o.y = g_p[sd2.z] + g_q[sd2.w] + b;
        ((float2*)out)[t] = o;
    } else {
        int2 sd = g_sd[e];
        out[e] = g_p[sd.x] + g_q[sd.y] + b;
    }
}

// ---------------- launch ----------------
extern "C" void kernel_launch(void* const* d_in, const int* in_sizes, int n_in,
                              void* d_out, int out_size)
{
    const float* x     = (const float*)d_in[0];
    const void*  ei    = d_in[1];
    const float* ea    = (const float*)d_in[2];
    const float* W_em  = (const float*)d_in[3];
    const float* b_em  = (const float*)d_in[4];
    const float* W0    = (const float*)d_in[5];
    const float* b0    = (const float*)d_in[6];
    const float* Wl1   = (const float*)d_in[7];
    const float* bl1   = (const float*)d_in[8];
    const float* Wr1   = (const float*)d_in[9];
    const float* br1   = (const float*)d_in[10];
    const float* We1   = (const float*)d_in[11];
    const float* att1  = (const float*)d_in[12];
    const float* bias1 = (const float*)d_in[13];
    const float* Wl2   = (const float*)d_in[14];
    const float* bl2   = (const float*)d_in[15];
    const float* Wr2   = (const float*)d_in[16];
    const float* br2   = (const float*)d_in[17];
    const float* We2   = (const float*)d_in[18];
    const float* att2  = (const float*)d_in[19];
    const float* bias2 = (const float*)d_in[20];
    const float* Wd    = (const float*)d_in[21];
    const float* bd    = (const float*)d_in[22];
    float* out = (float*)d_out;

    int N = in_sizes[0];
    int E = in_sizes[2];
    int NB = (N + SCAN_TILE - 1) / SCAN_TILE;
    int Eh = (E + 1) / 2;
    int Eq = (E + 3) / 4;

    k_prez<<<(N + 255) / 256, 256>>>(W_em, b_em, W0, b0, Wl1, bl1, Wr1, br1, We1, We2,
                                     Wl2, bl2, bias2, Wd, ei, N);
    k_convert<<<(Eh + 255) / 256, 256>>>(ei, E);
    k_bsum<<<NB, 1024>>>(N);
    k_scan2<<<NB, 1024>>>(N, NB);
    k_scatter<<<(Eq + 255) / 256, 256>>>(ea, E);
    k_layer12<<<(N + 63) / 64, 256>>>(x, att1, bias1, Wl2, bl2, Wr2, br2, N);
    k_attn2<<<(N + 7) / 8, 256>>>(att2, N);
    k_final<<<(Eh + 255) / 256, 256>>>(bd, out, E);
}